// round 3
// baseline (speedup 1.0000x reference)
#include <cuda_runtime.h>
#include <cuda_bf16.h>

// Net: x[B,2] -> fc1(9) -> ELU -> 19 x (fc 9x9 -> ELU) -> fc(2) -> log_softmax
// fp32 packed f32x2 math: each thread handles ONE pair of batch rows packed
// into the two f32 halves of every register. Scale-domain ELU:
// activations stored as a = log2(e)*elu(z); mid weights unchanged,
// biases *= log2e, W1,b1 *= log2e, W21 *= 1/log2e.

#define THREADS 256

static const int B_ROWS      = 2097152;
static const int NPAIR       = B_ROWS / 2;            // 1,048,576 threads
static const int NBLOCK      = NPAIR / THREADS;       // 4096

typedef unsigned long long u64;

#define L2E  1.4426950408889634f
#define IL2E 0.6931471805599453f

// shared layout (u64 units). Mid rows: [w0..w8, bias] = 10 u64 = 5 x LDS.128.
#define OFF_MW   0                   // 19 * 9 * 10 = 1710 ; layer l, row j at l*90+j*10
#define OFF_W1   1710                // 9 rows * 4 : [w0,w1,bias,pad]          (scaled L2E)
#define OFF_W21  1746                // 2 rows * 10: [w0..w8, bias]            (W scaled 1/L2E)
#define SW_TOT   1766                // 14128 bytes

__device__ __forceinline__ u64 pk2(float lo, float hi) {
    u64 r; asm("mov.b64 %0,{%1,%2};" : "=l"(r) : "f"(lo), "f"(hi)); return r;
}
__device__ __forceinline__ void upk2(float& lo, float& hi, u64 v) {
    asm("mov.b64 {%0,%1},%2;" : "=f"(lo), "=f"(hi) : "l"(v));
}
__device__ __forceinline__ u64 ffma2(u64 a, u64 b, u64 c) {
    u64 d; asm("fma.rn.f32x2 %0,%1,%2,%3;" : "=l"(d) : "l"(a), "l"(b), "l"(c)); return d;
}
__device__ __forceinline__ float ex2(float x) {
    float r; asm("ex2.approx.ftz.f32 %0, %1;" : "=f"(r) : "f"(x)); return r;
}

// scale-domain packed ELU (3 ops per half):
//   out = max(a, fma(EX2(-|a|), L2E, -L2E))
// a>0: exp term < 0  -> returns exact a.   a<=0: EX2(a)*L2E - L2E = L2E*(e^z - 1). 
// EX2 input is always <= 0 -> no overflow.
__device__ __forceinline__ u64 elu2s(u64 v) {
    float lo, hi; upk2(lo, hi, v);
    float elo = ex2(-fabsf(lo));
    float ehi = ex2(-fabsf(hi));
    float rlo = fmaxf(lo, fmaf(elo, L2E, -L2E));
    float rhi = fmaxf(hi, fmaf(ehi, L2E, -L2E));
    return pk2(rlo, rhi);
}

// log_softmax over 2 logits
__device__ __forceinline__ void lsm2(float l0, float l1, float& o0, float& o1) {
    float m   = fmaxf(l0, l1);
    float t   = __expf(-fabsf(l0 - l1));
    float lse = m + log1pf(t);
    o0 = l0 - lse;
    o1 = l1 - lse;
}

// one 9x9 mid layer + ELU, in -> out. Row j: 5 x LDS.128 (w0..w8 + bias).
__device__ __forceinline__ void mid_layer(const u64* __restrict__ wl,
                                          u64 (&in)[9], u64 (&out)[9])
{
#pragma unroll
    for (int j = 0; j < 9; j++) {
        const u64* wr = wl + j * 10;
        ulonglong2 w01 = *reinterpret_cast<const ulonglong2*>(wr + 0);
        ulonglong2 w23 = *reinterpret_cast<const ulonglong2*>(wr + 2);
        ulonglong2 w45 = *reinterpret_cast<const ulonglong2*>(wr + 4);
        ulonglong2 w67 = *reinterpret_cast<const ulonglong2*>(wr + 6);
        ulonglong2 w8b = *reinterpret_cast<const ulonglong2*>(wr + 8);

        u64 acc = ffma2(w8b.x, in[8], w8b.y);     // bias + w8*in8
        acc = ffma2(w01.x, in[0], acc);
        acc = ffma2(w01.y, in[1], acc);
        acc = ffma2(w23.x, in[2], acc);
        acc = ffma2(w23.y, in[3], acc);
        acc = ffma2(w45.x, in[4], acc);
        acc = ffma2(w45.y, in[5], acc);
        acc = ffma2(w67.x, in[6], acc);
        acc = ffma2(w67.y, in[7], acc);
        out[j] = elu2s(acc);
    }
}

__global__ void __launch_bounds__(THREADS, 3)
mlp_kernel(const float* __restrict__ x,
           const float* __restrict__ W1,  const float* __restrict__ b1,
           const float* __restrict__ Wm,  const float* __restrict__ bm,
           const float* __restrict__ W21, const float* __restrict__ b21,
           float* __restrict__ out)
{
    __shared__ __align__(16) u64 sw[SW_TOT];
    const int t = threadIdx.x;

    // Stage weights into shared: duplicated into both f32x2 halves, scaled.
    for (int i = t; i < 19 * 81; i += THREADS) {
        int l = i / 81, r = i % 81;
        int j = r / 9,  k = r % 9;
        float v = Wm[i];                               // mid W unscaled
        sw[OFF_MW + l * 90 + j * 10 + k] = pk2(v, v);
    }
    for (int i = t; i < 19 * 9; i += THREADS) {
        int l = i / 9, j = i % 9;
        float v = bm[i] * L2E;
        sw[OFF_MW + l * 90 + j * 10 + 9] = pk2(v, v);  // bias in slot 9
    }
    if (t < 9) {
        sw[OFF_W1 + t * 4 + 0] = pk2(W1[t * 2 + 0] * L2E, W1[t * 2 + 0] * L2E);
        sw[OFF_W1 + t * 4 + 1] = pk2(W1[t * 2 + 1] * L2E, W1[t * 2 + 1] * L2E);
        sw[OFF_W1 + t * 4 + 2] = pk2(b1[t] * L2E,          b1[t] * L2E);
        sw[OFF_W1 + t * 4 + 3] = 0ull;
    }
    if (t >= 32 && t < 50) {                            // 18 W21 entries
        int i = t - 32;
        int o = i / 9, k = i % 9;
        float v = W21[i] * IL2E;
        sw[OFF_W21 + o * 10 + k] = pk2(v, v);
    }
    if (t >= 64 && t < 66) {
        int o = t - 64;
        sw[OFF_W21 + o * 10 + 9] = pk2(b21[o], b21[o]);
    }
    __syncthreads();

    const int gtid = blockIdx.x * THREADS + t;

    // One float4 = rows (2*gtid, 2*gtid+1), 2 features each. Coalesced.
    float4 xin = reinterpret_cast<const float4*>(x)[gtid];
    u64 x0 = pk2(xin.x, xin.z);   // feature 0 of row A / row B
    u64 x1 = pk2(xin.y, xin.w);   // feature 1

    u64 h[9], g[9];

    // ---- fc1 (pre-scaled by L2E) + ELU ----
#pragma unroll
    for (int j = 0; j < 9; j++) {
        ulonglong2 wa = *reinterpret_cast<const ulonglong2*>(&sw[OFF_W1 + j * 4]);
        ulonglong2 wb = *reinterpret_cast<const ulonglong2*>(&sw[OFF_W1 + j * 4 + 2]);
        u64 acc = ffma2(wa.x, x0, wb.x);   // w0*x0 + bias
        acc     = ffma2(wa.y, x1, acc);
        h[j] = elu2s(acc);
    }

    // ---- 19 mid layers: 9 x (h->g, g->h) + final h->g ----
#pragma unroll 1
    for (int l = 0; l < 9; l++) {
        mid_layer(&sw[OFF_MW + (2 * l)     * 90], h, g);
        mid_layer(&sw[OFF_MW + (2 * l + 1) * 90], g, h);
    }
    mid_layer(&sw[OFF_MW + 18 * 90], h, g);

    // ---- output layer (W21 pre-scaled 1/L2E) + log_softmax ----
    u64 a01[2];
#pragma unroll
    for (int o = 0; o < 2; o++) {
        const u64* wr = &sw[OFF_W21 + o * 10];
        ulonglong2 w01 = *reinterpret_cast<const ulonglong2*>(wr + 0);
        ulonglong2 w23 = *reinterpret_cast<const ulonglong2*>(wr + 2);
        ulonglong2 w45 = *reinterpret_cast<const ulonglong2*>(wr + 4);
        ulonglong2 w67 = *reinterpret_cast<const ulonglong2*>(wr + 6);
        ulonglong2 w8b = *reinterpret_cast<const ulonglong2*>(wr + 8);
        u64 acc = ffma2(w8b.x, g[8], w8b.y);
        acc = ffma2(w01.x, g[0], acc);
        acc = ffma2(w01.y, g[1], acc);
        acc = ffma2(w23.x, g[2], acc);
        acc = ffma2(w23.y, g[3], acc);
        acc = ffma2(w45.x, g[4], acc);
        acc = ffma2(w45.y, g[5], acc);
        acc = ffma2(w67.x, g[6], acc);
        acc = ffma2(w67.y, g[7], acc);
        a01[o] = acc;
    }

    float l0A, l0B, l1A, l1B;
    upk2(l0A, l0B, a01[0]);
    upk2(l1A, l1B, a01[1]);

    float4 o;
    lsm2(l0A, l1A, o.x, o.y);   // row A: out[2g][0..1]
    lsm2(l0B, l1B, o.z, o.w);   // row B
    reinterpret_cast<float4*>(out)[gtid] = o;
}

extern "C" void kernel_launch(void* const* d_in, const int* in_sizes, int n_in,
                              void* d_out, int out_size)
{
    const float* x   = (const float*)d_in[0];
    const float* W1  = (const float*)d_in[1];
    const float* b1  = (const float*)d_in[2];
    const float* Wm  = (const float*)d_in[3];
    const float* bm  = (const float*)d_in[4];
    const float* W21 = (const float*)d_in[5];
    const float* b21 = (const float*)d_in[6];
    float*       out = (float*)d_out;

    mlp_kernel<<<NBLOCK, THREADS>>>(x, W1, b1, Wm, bm, W21, b21, out);
}

// round 4
// speedup vs baseline: 1.1304x; 1.1304x over previous
#include <cuda_runtime.h>
#include <cuda_bf16.h>

// Net: x[B,2] -> fc1(9) -> ELU -> 19 x (fc 9x9 -> ELU) -> fc(2) -> log_softmax
// fp32 packed f32x2 math, NP=2 row-pairs/thread (4 batch rows) to amortize LDS.
// Scale-domain ELU: activations a = log2(e)*elu(z); mid W unchanged, biases *L2E,
// W1,b1 *L2E, W21 *1/L2E.

#define THREADS 128
#define NP 2

static const int B_ROWS      = 2097152;
static const int NPAIR       = B_ROWS / 2;              // 1,048,576
static const int TOT_THREADS = NPAIR / NP;              // 524,288
static const int NBLOCK      = TOT_THREADS / THREADS;   // 4096

typedef unsigned long long u64;

#define L2E  1.4426950408889634f
#define IL2E 0.6931471805599453f
#define LN2  0.6931471805599453f

// shared layout (u64 units). Mid rows: [w0..w8, bias] = 10 u64 = 5 x LDS.128.
#define OFF_MW   0                   // 19*90 ; layer l row j at l*90 + j*10
#define OFF_W1   1710                // 9 rows * 4 : [w0, w1, bias, pad]   (scaled L2E)
#define OFF_W21  1746                // 2 rows * 10: [w0..w8, bias]        (W scaled 1/L2E)
#define SW_TOT   1766

__device__ __forceinline__ u64 pk2(float lo, float hi) {
    u64 r; asm("mov.b64 %0,{%1,%2};" : "=l"(r) : "f"(lo), "f"(hi)); return r;
}
__device__ __forceinline__ void upk2(float& lo, float& hi, u64 v) {
    asm("mov.b64 {%0,%1},%2;" : "=f"(lo), "=f"(hi) : "l"(v));
}
__device__ __forceinline__ u64 ffma2(u64 a, u64 b, u64 c) {
    u64 d; asm("fma.rn.f32x2 %0,%1,%2,%3;" : "=l"(d) : "l"(a), "l"(b), "l"(c)); return d;
}
__device__ __forceinline__ float ex2(float x) {
    float r; asm("ex2.approx.ftz.f32 %0, %1;" : "=f"(r) : "f"(x)); return r;
}
__device__ __forceinline__ float lg2(float x) {
    float r; asm("lg2.approx.ftz.f32 %0, %1;" : "=f"(r) : "f"(x)); return r;
}

// scale-domain packed ELU:
//   e   = {EX2(-|lo|), EX2(-|hi|)}          (2 MUFU, abs/neg fold into source mods)
//   r   = ffma2(e, {L2E}, {-L2E})           (1 packed FMA)
//   out = {max(lo, r.lo), max(hi, r.hi)}    (2 FMNMX)
// a>0: r<0 so max returns exact a.  a<=0: L2E*(e^z - 1). EX2 arg <= 0, no overflow.
__device__ __forceinline__ u64 elu2s(u64 v) {
    float lo, hi; upk2(lo, hi, v);
    float elo = ex2(-fabsf(lo));
    float ehi = ex2(-fabsf(hi));
    u64 r = ffma2(pk2(elo, ehi), pk2(L2E, L2E), pk2(-L2E, -L2E));
    float rlo, rhi; upk2(rlo, rhi, r);
    return pk2(fmaxf(lo, rlo), fmaxf(hi, rhi));
}

// log_softmax over 2 logits, MUFU-based:
// lse = max + ln2 * lg2(1 + 2^(-|d|*log2e)),  d = l0-l1
__device__ __forceinline__ void lsm2(float l0, float l1, float& o0, float& o1) {
    float m   = fmaxf(l0, l1);
    float t   = ex2(-fabsf(l0 - l1) * L2E);
    float lse = fmaf(lg2(1.0f + t), LN2, m);
    o0 = l0 - lse;
    o1 = l1 - lse;
}

// one 9x9 mid layer + ELU for both pairs. Row j: 5 x LDS.128 (w0..w8 + bias).
__device__ __forceinline__ void mid_layer(const u64* __restrict__ wl,
                                          u64 (&in)[NP][9], u64 (&out)[NP][9])
{
#pragma unroll
    for (int j = 0; j < 9; j++) {
        const u64* wr = wl + j * 10;
        ulonglong2 w8b = *reinterpret_cast<const ulonglong2*>(wr + 8);
        u64 a0 = ffma2(w8b.x, in[0][8], w8b.y);
        u64 a1 = ffma2(w8b.x, in[1][8], w8b.y);
        ulonglong2 w01 = *reinterpret_cast<const ulonglong2*>(wr + 0);
        a0 = ffma2(w01.x, in[0][0], a0);  a1 = ffma2(w01.x, in[1][0], a1);
        a0 = ffma2(w01.y, in[0][1], a0);  a1 = ffma2(w01.y, in[1][1], a1);
        ulonglong2 w23 = *reinterpret_cast<const ulonglong2*>(wr + 2);
        a0 = ffma2(w23.x, in[0][2], a0);  a1 = ffma2(w23.x, in[1][2], a1);
        a0 = ffma2(w23.y, in[0][3], a0);  a1 = ffma2(w23.y, in[1][3], a1);
        ulonglong2 w45 = *reinterpret_cast<const ulonglong2*>(wr + 4);
        a0 = ffma2(w45.x, in[0][4], a0);  a1 = ffma2(w45.x, in[1][4], a1);
        a0 = ffma2(w45.y, in[0][5], a0);  a1 = ffma2(w45.y, in[1][5], a1);
        ulonglong2 w67 = *reinterpret_cast<const ulonglong2*>(wr + 6);
        a0 = ffma2(w67.x, in[0][6], a0);  a1 = ffma2(w67.x, in[1][6], a1);
        a0 = ffma2(w67.y, in[0][7], a0);  a1 = ffma2(w67.y, in[1][7], a1);
        out[0][j] = elu2s(a0);
        out[1][j] = elu2s(a1);
    }
}

__global__ void __launch_bounds__(THREADS, 5)
mlp_kernel(const float* __restrict__ x,
           const float* __restrict__ W1,  const float* __restrict__ b1,
           const float* __restrict__ Wm,  const float* __restrict__ bm,
           const float* __restrict__ W21, const float* __restrict__ b21,
           float* __restrict__ out)
{
    __shared__ __align__(16) u64 sw[SW_TOT];
    const int t = threadIdx.x;

    // Stage weights into shared, duplicated {w,w}, scaled per plan.
    for (int i = t; i < 19 * 81; i += THREADS) {
        int l = i / 81, r = i % 81;
        int j = r / 9,  k = r % 9;
        float v = Wm[i];
        sw[OFF_MW + l * 90 + j * 10 + k] = pk2(v, v);
    }
    for (int i = t; i < 19 * 9; i += THREADS) {
        int l = i / 9, j = i % 9;
        float v = bm[i] * L2E;
        sw[OFF_MW + l * 90 + j * 10 + 9] = pk2(v, v);
    }
    if (t < 9) {
        float w0 = W1[t * 2 + 0] * L2E;
        float w1 = W1[t * 2 + 1] * L2E;
        float bb = b1[t] * L2E;
        sw[OFF_W1 + t * 4 + 0] = pk2(w0, w0);
        sw[OFF_W1 + t * 4 + 1] = pk2(w1, w1);
        sw[OFF_W1 + t * 4 + 2] = pk2(bb, bb);
        sw[OFF_W1 + t * 4 + 3] = 0ull;
    }
    if (t >= 32 && t < 50) {
        int i = t - 32;
        int o = i / 9, k = i % 9;
        float v = W21[i] * IL2E;
        sw[OFF_W21 + o * 10 + k] = pk2(v, v);
    }
    if (t >= 64 && t < 66) {
        int o = t - 64;
        sw[OFF_W21 + o * 10 + 9] = pk2(b21[o], b21[o]);
    }
    __syncthreads();

    const int gtid = blockIdx.x * THREADS + t;

    int pidx[NP];
    u64 h[NP][9], g[NP][9];

    // ---- input load + fc1 (pre-scaled L2E) + ELU ----
#pragma unroll
    for (int p = 0; p < NP; p++) {
        pidx[p] = gtid + p * TOT_THREADS;              // strided -> coalesced
        float4 xin = reinterpret_cast<const float4*>(x)[pidx[p]];
        u64 x0 = pk2(xin.x, xin.z);
        u64 x1 = pk2(xin.y, xin.w);
#pragma unroll
        for (int j = 0; j < 9; j++) {
            ulonglong2 wa = *reinterpret_cast<const ulonglong2*>(&sw[OFF_W1 + j * 4]);
            ulonglong2 wb = *reinterpret_cast<const ulonglong2*>(&sw[OFF_W1 + j * 4 + 2]);
            u64 acc = ffma2(wa.x, x0, wb.x);
            acc     = ffma2(wa.y, x1, acc);
            h[p][j] = elu2s(acc);
        }
    }

    // ---- 19 mid layers: 9 x (h->g, g->h) + final h->g ----
#pragma unroll 1
    for (int l = 0; l < 9; l++) {
        mid_layer(&sw[OFF_MW + (2 * l)     * 90], h, g);
        mid_layer(&sw[OFF_MW + (2 * l + 1) * 90], g, h);
    }
    mid_layer(&sw[OFF_MW + 18 * 90], h, g);

    // ---- output layer (W21 pre-scaled 1/L2E) + log_softmax ----
#pragma unroll
    for (int p = 0; p < NP; p++) {
        u64 a01[2];
#pragma unroll
        for (int o = 0; o < 2; o++) {
            const u64* wr = &sw[OFF_W21 + o * 10];
            ulonglong2 w8b = *reinterpret_cast<const ulonglong2*>(wr + 8);
            u64 acc = ffma2(w8b.x, g[p][8], w8b.y);
            ulonglong2 w01 = *reinterpret_cast<const ulonglong2*>(wr + 0);
            acc = ffma2(w01.x, g[p][0], acc);
            acc = ffma2(w01.y, g[p][1], acc);
            ulonglong2 w23 = *reinterpret_cast<const ulonglong2*>(wr + 2);
            acc = ffma2(w23.x, g[p][2], acc);
            acc = ffma2(w23.y, g[p][3], acc);
            ulonglong2 w45 = *reinterpret_cast<const ulonglong2*>(wr + 4);
            acc = ffma2(w45.x, g[p][4], acc);
            acc = ffma2(w45.y, g[p][5], acc);
            ulonglong2 w67 = *reinterpret_cast<const ulonglong2*>(wr + 6);
            acc = ffma2(w67.x, g[p][6], acc);
            acc = ffma2(w67.y, g[p][7], acc);
            a01[o] = acc;
        }

        float l0A, l0B, l1A, l1B;
        upk2(l0A, l0B, a01[0]);
        upk2(l1A, l1B, a01[1]);

        float4 o;
        lsm2(l0A, l1A, o.x, o.y);
        lsm2(l0B, l1B, o.z, o.w);
        reinterpret_cast<float4*>(out)[pidx[p]] = o;
    }
}

extern "C" void kernel_launch(void* const* d_in, const int* in_sizes, int n_in,
                              void* d_out, int out_size)
{
    const float* x   = (const float*)d_in[0];
    const float* W1  = (const float*)d_in[1];
    const float* b1  = (const float*)d_in[2];
    const float* Wm  = (const float*)d_in[3];
    const float* bm  = (const float*)d_in[4];
    const float* W21 = (const float*)d_in[5];
    const float* b21 = (const float*)d_in[6];
    float*       out = (float*)d_out;

    mlp_kernel<<<NBLOCK, THREADS>>>(x, W1, b1, Wm, bm, W21, b21, out);
}

// round 5
// speedup vs baseline: 1.2012x; 1.0626x over previous
#include <cuda_runtime.h>
#include <cuda_bf16.h>

// Net: x[B,2] -> fc1(9) -> ELU -> 19 x (fc 9x9 -> ELU) -> fc(2) -> log_softmax
// fp32 packed f32x2 math, NP=2 row-pairs/thread (4 batch rows) to amortize LDS.
// Scale-domain ELU: activations a = log2(e)*elu(z); mid W unchanged, biases *L2E,
// W1,b1 *L2E, W21 *1/L2E.

#define THREADS 128
#define NP 2

static const int B_ROWS      = 2097152;
static const int NPAIR       = B_ROWS / 2;              // 1,048,576
static const int TOT_THREADS = NPAIR / NP;              // 524,288
static const int NBLOCK      = TOT_THREADS / THREADS;   // 4096

typedef unsigned long long u64;

#define L2E  1.4426950408889634f
#define IL2E 0.6931471805599453f
#define LN2  0.6931471805599453f

// shared layout (u64 units). Mid rows: [w0..w8, bias] = 10 u64 = 5 x LDS.128.
#define OFF_MW   0                   // 19*90 ; layer l row j at l*90 + j*10
#define OFF_W1   1710                // 9 rows * 4 : [w0, w1, bias, pad]   (scaled L2E)
#define OFF_W21  1746                // 2 rows * 10: [w0..w8, bias]        (W scaled 1/L2E)
#define SW_TOT   1766

__device__ __forceinline__ u64 pk2(float lo, float hi) {
    u64 r; asm("mov.b64 %0,{%1,%2};" : "=l"(r) : "f"(lo), "f"(hi)); return r;
}
__device__ __forceinline__ void upk2(float& lo, float& hi, u64 v) {
    asm("mov.b64 {%0,%1},%2;" : "=f"(lo), "=f"(hi) : "l"(v));
}
__device__ __forceinline__ u64 ffma2(u64 a, u64 b, u64 c) {
    u64 d; asm("fma.rn.f32x2 %0,%1,%2,%3;" : "=l"(d) : "l"(a), "l"(b), "l"(c)); return d;
}
__device__ __forceinline__ float ex2(float x) {
    float r; asm("ex2.approx.ftz.f32 %0, %1;" : "=f"(r) : "f"(x)); return r;
}
__device__ __forceinline__ float lg2(float x) {
    float r; asm("lg2.approx.ftz.f32 %0, %1;" : "=f"(r) : "f"(x)); return r;
}

// scale-domain packed ELU:
//   e   = {EX2(-|lo|), EX2(-|hi|)}   (neg-abs folds into MUFU source modifier)
//   r   = ffma2(e, {L2E}, {-L2E})
//   out = {max(lo,r.lo), max(hi,r.hi)}   (FMNMX -> alu pipe)
// a>0: r<0 so max returns exact a.  a<=0: L2E*(e^z-1).  EX2 arg <= 0, no overflow.
__device__ __forceinline__ u64 elu2s(u64 v) {
    float lo, hi; upk2(lo, hi, v);
    float elo = ex2(-fabsf(lo));
    float ehi = ex2(-fabsf(hi));
    u64 r = ffma2(pk2(elo, ehi), pk2(L2E, L2E), pk2(-L2E, -L2E));
    float rlo, rhi; upk2(rlo, rhi, r);
    return pk2(fmaxf(lo, rlo), fmaxf(hi, rhi));
}

// log_softmax over 2 logits, MUFU-based:
// lse = max + ln2 * lg2(1 + 2^(-|d|*log2e))
__device__ __forceinline__ void lsm2(float l0, float l1, float& o0, float& o1) {
    float m   = fmaxf(l0, l1);
    float t   = ex2(-fabsf(l0 - l1) * L2E);
    float lse = fmaf(lg2(1.0f + t), LN2, m);
    o0 = l0 - lse;
    o1 = l1 - lse;
}

// one 9x9 mid layer + ELU for both pairs. Row j: load ALL 5 x LDS.128 up
// front, then run the two independent FMA chains. Rows are independent, so
// with a 128-reg budget ptxas can pipeline next-row loads under this row's
// chain and keep 2-3 rows in flight.
__device__ __forceinline__ void mid_layer(const u64* __restrict__ wl,
                                          u64 (&in)[NP][9], u64 (&out)[NP][9])
{
#pragma unroll
    for (int j = 0; j < 9; j++) {
        const u64* wr = wl + j * 10;
        ulonglong2 w01 = *reinterpret_cast<const ulonglong2*>(wr + 0);
        ulonglong2 w23 = *reinterpret_cast<const ulonglong2*>(wr + 2);
        ulonglong2 w45 = *reinterpret_cast<const ulonglong2*>(wr + 4);
        ulonglong2 w67 = *reinterpret_cast<const ulonglong2*>(wr + 6);
        ulonglong2 w8b = *reinterpret_cast<const ulonglong2*>(wr + 8);

        u64 a0 = ffma2(w8b.x, in[0][8], w8b.y);
        u64 a1 = ffma2(w8b.x, in[1][8], w8b.y);
        a0 = ffma2(w01.x, in[0][0], a0);  a1 = ffma2(w01.x, in[1][0], a1);
        a0 = ffma2(w01.y, in[0][1], a0);  a1 = ffma2(w01.y, in[1][1], a1);
        a0 = ffma2(w23.x, in[0][2], a0);  a1 = ffma2(w23.x, in[1][2], a1);
        a0 = ffma2(w23.y, in[0][3], a0);  a1 = ffma2(w23.y, in[1][3], a1);
        a0 = ffma2(w45.x, in[0][4], a0);  a1 = ffma2(w45.x, in[1][4], a1);
        a0 = ffma2(w45.y, in[0][5], a0);  a1 = ffma2(w45.y, in[1][5], a1);
        a0 = ffma2(w67.x, in[0][6], a0);  a1 = ffma2(w67.x, in[1][6], a1);
        a0 = ffma2(w67.y, in[0][7], a0);  a1 = ffma2(w67.y, in[1][7], a1);
        out[0][j] = elu2s(a0);
        out[1][j] = elu2s(a1);
    }
}

__global__ void __launch_bounds__(THREADS, 4)
mlp_kernel(const float* __restrict__ x,
           const float* __restrict__ W1,  const float* __restrict__ b1,
           const float* __restrict__ Wm,  const float* __restrict__ bm,
           const float* __restrict__ W21, const float* __restrict__ b21,
           float* __restrict__ out)
{
    __shared__ __align__(16) u64 sw[SW_TOT];
    const int t = threadIdx.x;
    const int gtid = blockIdx.x * THREADS + t;

    // Kick off the input loads FIRST so DRAM latency overlaps weight staging.
    int pidx[NP];
    float4 xin[NP];
#pragma unroll
    for (int p = 0; p < NP; p++) {
        pidx[p] = gtid + p * TOT_THREADS;              // strided -> coalesced
        xin[p]  = reinterpret_cast<const float4*>(x)[pidx[p]];
    }

    // Stage weights into shared, duplicated {w,w}, scaled per plan.
    for (int i = t; i < 19 * 81; i += THREADS) {
        int l = i / 81, r = i % 81;
        int j = r / 9,  k = r % 9;
        float v = Wm[i];
        sw[OFF_MW + l * 90 + j * 10 + k] = pk2(v, v);
    }
    for (int i = t; i < 19 * 9; i += THREADS) {
        int l = i / 9, j = i % 9;
        float v = bm[i] * L2E;
        sw[OFF_MW + l * 90 + j * 10 + 9] = pk2(v, v);
    }
    if (t < 9) {
        float w0 = W1[t * 2 + 0] * L2E;
        float w1 = W1[t * 2 + 1] * L2E;
        float bb = b1[t] * L2E;
        sw[OFF_W1 + t * 4 + 0] = pk2(w0, w0);
        sw[OFF_W1 + t * 4 + 1] = pk2(w1, w1);
        sw[OFF_W1 + t * 4 + 2] = pk2(bb, bb);
        sw[OFF_W1 + t * 4 + 3] = 0ull;
    }
    if (t >= 32 && t < 50) {
        int i = t - 32;
        int o = i / 9, k = i % 9;
        float v = W21[i] * IL2E;
        sw[OFF_W21 + o * 10 + k] = pk2(v, v);
    }
    if (t >= 64 && t < 66) {
        int o = t - 64;
        sw[OFF_W21 + o * 10 + 9] = pk2(b21[o], b21[o]);
    }
    __syncthreads();

    u64 h[NP][9], g[NP][9];

    // ---- fc1 (pre-scaled L2E) + ELU ----
#pragma unroll
    for (int p = 0; p < NP; p++) {
        u64 x0 = pk2(xin[p].x, xin[p].z);
        u64 x1 = pk2(xin[p].y, xin[p].w);
#pragma unroll
        for (int j = 0; j < 9; j++) {
            ulonglong2 wa = *reinterpret_cast<const ulonglong2*>(&sw[OFF_W1 + j * 4]);
            ulonglong2 wb = *reinterpret_cast<const ulonglong2*>(&sw[OFF_W1 + j * 4 + 2]);
            u64 acc = ffma2(wa.x, x0, wb.x);
            acc     = ffma2(wa.y, x1, acc);
            h[p][j] = elu2s(acc);
        }
    }

    // ---- 19 mid layers: 9 x (h->g, g->h) + final h->g ----
#pragma unroll 1
    for (int l = 0; l < 9; l++) {
        mid_layer(&sw[OFF_MW + (2 * l)     * 90], h, g);
        mid_layer(&sw[OFF_MW + (2 * l + 1) * 90], g, h);
    }
    mid_layer(&sw[OFF_MW + 18 * 90], h, g);

    // ---- output layer (W21 pre-scaled 1/L2E) + log_softmax ----
#pragma unroll
    for (int p = 0; p < NP; p++) {
        u64 a01[2];
#pragma unroll
        for (int o = 0; o < 2; o++) {
            const u64* wr = &sw[OFF_W21 + o * 10];
            ulonglong2 w01 = *reinterpret_cast<const ulonglong2*>(wr + 0);
            ulonglong2 w23 = *reinterpret_cast<const ulonglong2*>(wr + 2);
            ulonglong2 w45 = *reinterpret_cast<const ulonglong2*>(wr + 4);
            ulonglong2 w67 = *reinterpret_cast<const ulonglong2*>(wr + 6);
            ulonglong2 w8b = *reinterpret_cast<const ulonglong2*>(wr + 8);
            u64 acc = ffma2(w8b.x, g[p][8], w8b.y);
            acc = ffma2(w01.x, g[p][0], acc);
            acc = ffma2(w01.y, g[p][1], acc);
            acc = ffma2(w23.x, g[p][2], acc);
            acc = ffma2(w23.y, g[p][3], acc);
            acc = ffma2(w45.x, g[p][4], acc);
            acc = ffma2(w45.y, g[p][5], acc);
            acc = ffma2(w67.x, g[p][6], acc);
            acc = ffma2(w67.y, g[p][7], acc);
            a01[o] = acc;
        }

        float l0A, l0B, l1A, l1B;
        upk2(l0A, l0B, a01[0]);
        upk2(l1A, l1B, a01[1]);

        float4 o;
        lsm2(l0A, l1A, o.x, o.y);
        lsm2(l0B, l1B, o.z, o.w);
        reinterpret_cast<float4*>(out)[pidx[p]] = o;
    }
}

extern "C" void kernel_launch(void* const* d_in, const int* in_sizes, int n_in,
                              void* d_out, int out_size)
{
    const float* x   = (const float*)d_in[0];
    const float* W1  = (const float*)d_in[1];
    const float* b1  = (const float*)d_in[2];
    const float* Wm  = (const float*)d_in[3];
    const float* bm  = (const float*)d_in[4];
    const float* W21 = (const float*)d_in[5];
    const float* b21 = (const float*)d_in[6];
    float*       out = (float*)d_out;

    mlp_kernel<<<NBLOCK, THREADS>>>(x, W1, b1, Wm, bm, W21, b21, out);
}